// round 1
// baseline (speedup 1.0000x reference)
#include <cuda_runtime.h>
#include <math.h>
#include <stdint.h>

#define BB 2
#define SS 2048
#define HIDD 2048
#define NHH 8
#define NKVV 1
#define HDD 256

// ---------------- scratch (device globals; no allocation allowed) -----------
__device__ float g_q[(size_t)BB * SS * NHH * HDD];       // 33.5 MB
__device__ float g_k[(size_t)BB * SS * NKVV * HDD];      // 4 MB
__device__ float g_v[(size_t)BB * SS * NKVV * HDD];      // 4 MB
__device__ float g_scores[(size_t)BB * NHH * SS * SS];   // 268 MB
__device__ float g_ctx[(size_t)BB * SS * NHH * HDD];     // 33.5 MB

// ---------------- generic batched tiled SGEMM (128x128x8, 8x8 microtile) ----
// C[m,n] = sum_k A[m,k] * B[k,n]        (TRANSB=false, B is [K,N] ld=ldb)
// C[m,n] = sum_k A[m,k] * B[n,k]        (TRANSB=true,  B is [N,K] ld=ldb)
// Batch index z = b*nh + h; per-matrix offset = b*s?b + h*s?h.
template <bool TRANSB>
__global__ __launch_bounds__(256) void gemm_kernel(
    const float* __restrict__ A, const float* __restrict__ B,
    float* __restrict__ C,
    int M, int N, int K, int lda, int ldb, int ldc,
    long long sAb, long long sAh, long long sBb, long long sBh,
    long long sCb, long long sCh, int nh)
{
    const int z = blockIdx.z;
    const int b = z / nh, h = z % nh;
    A += (size_t)b * sAb + (size_t)h * sAh;
    B += (size_t)b * sBb + (size_t)h * sBh;
    C += (size_t)b * sCb + (size_t)h * sCh;

    __shared__ float As[8][128];
    __shared__ float Bs[8][128];

    const int tid = threadIdx.x;            // 256 threads
    const int bm = blockIdx.y * 128;
    const int bn = blockIdx.x * 128;
    const int tx = tid & 15, ty = tid >> 4;
    const int row0 = ty * 8, col0 = tx * 8;

    const int lr  = tid >> 1;               // 0..127
    const int lc4 = (tid & 1) * 4;          // 0 or 4

    float acc[8][8];
#pragma unroll
    for (int i = 0; i < 8; i++)
#pragma unroll
        for (int j = 0; j < 8; j++) acc[i][j] = 0.f;

    for (int k0 = 0; k0 < K; k0 += 8) {
        // A tile: 128(m) x 8(k), float4 along k, store transposed
        float4 av = *reinterpret_cast<const float4*>(
            A + (size_t)(bm + lr) * lda + k0 + lc4);
        As[lc4 + 0][lr] = av.x;
        As[lc4 + 1][lr] = av.y;
        As[lc4 + 2][lr] = av.z;
        As[lc4 + 3][lr] = av.w;

        if (TRANSB) {
            // B tile: 128(n) x 8(k) from row-major [N,K]
            float4 bv = *reinterpret_cast<const float4*>(
                B + (size_t)(bn + lr) * ldb + k0 + lc4);
            Bs[lc4 + 0][lr] = bv.x;
            Bs[lc4 + 1][lr] = bv.y;
            Bs[lc4 + 2][lr] = bv.z;
            Bs[lc4 + 3][lr] = bv.w;
        } else {
            // B tile: 8(k) x 128(n) from row-major [K,N]
            const int bk  = tid >> 5;        // 0..7
            const int bn4 = (tid & 31) * 4;  // 0..124
            *reinterpret_cast<float4*>(&Bs[bk][bn4]) =
                *reinterpret_cast<const float4*>(
                    B + (size_t)(k0 + bk) * ldb + bn + bn4);
        }
        __syncthreads();

#pragma unroll
        for (int kk = 0; kk < 8; kk++) {
            float a[8], bb[8];
#pragma unroll
            for (int i = 0; i < 8; i++) a[i] = As[kk][row0 + i];
#pragma unroll
            for (int j = 0; j < 8; j++) bb[j] = Bs[kk][col0 + j];
#pragma unroll
            for (int i = 0; i < 8; i++)
#pragma unroll
                for (int j = 0; j < 8; j++)
                    acc[i][j] = fmaf(a[i], bb[j], acc[i][j]);
        }
        __syncthreads();
    }

#pragma unroll
    for (int i = 0; i < 8; i++) {
        float4* cp = reinterpret_cast<float4*>(
            C + (size_t)(bm + row0 + i) * ldc + bn + col0);
        cp[0] = make_float4(acc[i][0], acc[i][1], acc[i][2], acc[i][3]);
        cp[1] = make_float4(acc[i][4], acc[i][5], acc[i][6], acc[i][7]);
    }
}

// ---------------- RoPE (in-place on [B,S,nheads*HD]) -------------------------
__global__ void rope_kernel(float* __restrict__ x,
                            const int* __restrict__ pos_ids, int nheads)
{
    const int half = HDD / 2;
    int idx = blockIdx.x * blockDim.x + threadIdx.x;
    int total = BB * SS * nheads * half;
    if (idx >= total) return;
    int d = idx % half;
    int t = idx / half;
    int h = t % nheads;
    int s = (t / nheads) % SS;
    int b = t / (nheads * SS);

    float pos = (float)pos_ids[b * SS + s];
    float inv = powf(10000.0f, -(2.0f * (float)d) / (float)HDD);
    float ang = pos * inv;
    float c = cosf(ang), sn = sinf(ang);

    size_t base = ((size_t)(b * SS + s) * nheads + h) * HDD;
    float x1 = x[base + d];
    float x2 = x[base + d + half];
    x[base + d]        = x1 * c - x2 * sn;
    x[base + d + half] = x2 * c + x1 * sn;
}

// ---------------- softmax over rows of scores, mask+scale fused -------------
// one 256-thread block per row of length S=2048 (8 elems/thread)
__global__ __launch_bounds__(256) void softmax_kernel(
    const float* __restrict__ scores, const float* __restrict__ mask,
    float* __restrict__ out, float scale)
{
    const int row = blockIdx.x;                 // b*NH*S + h*S + q
    const int q  = row % SS;
    const int b  = row / (NHH * SS);
    const float* srow = scores + (size_t)row * SS;
    const float* mrow = mask + ((size_t)b * SS + q) * SS;
    float* orow = out + (size_t)row * SS;

    const int tid = threadIdx.x;
    float vals[8];
    float mx = -INFINITY;
#pragma unroll
    for (int i = 0; i < 8; i++) {
        int k = tid + i * 256;
        float v = srow[k] * scale + mrow[k];
        vals[i] = v;
        mx = fmaxf(mx, v);
    }

    __shared__ float red[32];
    // warp max
#pragma unroll
    for (int o = 16; o > 0; o >>= 1)
        mx = fmaxf(mx, __shfl_xor_sync(0xFFFFFFFF, mx, o));
    if ((tid & 31) == 0) red[tid >> 5] = mx;
    __syncthreads();
    if (tid < 32) {
        float m = (tid < 8) ? red[tid] : -INFINITY;
#pragma unroll
        for (int o = 4; o > 0; o >>= 1)
            m = fmaxf(m, __shfl_xor_sync(0xFFFFFFFF, m, o));
        if (tid == 0) red[0] = m;
    }
    __syncthreads();
    mx = red[0];
    __syncthreads();

    float sum = 0.f;
#pragma unroll
    for (int i = 0; i < 8; i++) {
        vals[i] = __expf(vals[i] - mx);
        sum += vals[i];
    }
#pragma unroll
    for (int o = 16; o > 0; o >>= 1)
        sum += __shfl_xor_sync(0xFFFFFFFF, sum, o);
    if ((tid & 31) == 0) red[tid >> 5] = sum;
    __syncthreads();
    if (tid < 32) {
        float s = (tid < 8) ? red[tid] : 0.f;
#pragma unroll
        for (int o = 4; o > 0; o >>= 1)
            s += __shfl_xor_sync(0xFFFFFFFF, s, o);
        if (tid == 0) red[0] = s;
    }
    __syncthreads();
    float inv = 1.0f / red[0];

#pragma unroll
    for (int i = 0; i < 8; i++)
        orow[tid + i * 256] = vals[i] * inv;
}

// ---------------- launch ------------------------------------------------------
extern "C" void kernel_launch(void* const* d_in, const int* in_sizes, int n_in,
                              void* d_out, int out_size)
{
    const float* hid  = (const float*)d_in[0];  // [B,S,HID]
    const float* mask = (const float*)d_in[1];  // [B,1,S,S]
    const int*   pos  = (const int*)d_in[2];    // [B,S]
    const float* Wq   = (const float*)d_in[3];  // [HID, NH*HD]
    const float* Wk   = (const float*)d_in[4];  // [HID, NKV*HD]
    const float* Wv   = (const float*)d_in[5];
    const float* Wo   = (const float*)d_in[6];  // [NH*HD, HID]
    float* out = (float*)d_out;

    float *q, *k, *v, *scores, *ctx;
    cudaGetSymbolAddress((void**)&q, g_q);
    cudaGetSymbolAddress((void**)&k, g_k);
    cudaGetSymbolAddress((void**)&v, g_v);
    cudaGetSymbolAddress((void**)&scores, g_scores);
    cudaGetSymbolAddress((void**)&ctx, g_ctx);

    const long long OUT_ATT = (long long)BB * SS * HIDD;              // 8388608
    const long long OUT_W   = (long long)BB * NHH * SS * SS;          // 67108864
    float* attnp = ((long long)out_size >= OUT_ATT + OUT_W) ? (out + OUT_ATT)
                                                            : scores;

    const int M = BB * SS;  // 4096

    // Q = H @ Wq   [4096,2048]
    gemm_kernel<false><<<dim3(HIDD / 128, M / 128, 1), 256>>>(
        hid, Wq, q, M, NHH * HDD, HIDD, HIDD, NHH * HDD, NHH * HDD,
        0, 0, 0, 0, 0, 0, 1);
    // K = H @ Wk   [4096,256]
    gemm_kernel<false><<<dim3((NKVV * HDD) / 128, M / 128, 1), 256>>>(
        hid, Wk, k, M, NKVV * HDD, HIDD, HIDD, NKVV * HDD, NKVV * HDD,
        0, 0, 0, 0, 0, 0, 1);
    // V = H @ Wv   [4096,256]
    gemm_kernel<false><<<dim3((NKVV * HDD) / 128, M / 128, 1), 256>>>(
        hid, Wv, v, M, NKVV * HDD, HIDD, HIDD, NKVV * HDD, NKVV * HDD,
        0, 0, 0, 0, 0, 0, 1);

    // RoPE in place
    {
        int totq = BB * SS * NHH * (HDD / 2);
        rope_kernel<<<(totq + 255) / 256, 256>>>(q, pos, NHH);
        int totk = BB * SS * NKVV * (HDD / 2);
        rope_kernel<<<(totk + 255) / 256, 256>>>(k, pos, NKVV);
    }

    // scores[b,h] = Q[b,:,h] @ K[b]^T   M=S,N=S,K=HD  batches B*NH
    gemm_kernel<true><<<dim3(SS / 128, SS / 128, BB * NHH), 256>>>(
        q, k, scores, SS, SS, HDD,
        NHH * HDD, NKVV * HDD, SS,
        (long long)SS * NHH * HDD, HDD,           // A: per-b, per-h
        (long long)SS * NKVV * HDD, 0,            // B: per-b only
        (long long)NHH * SS * SS, (long long)SS * SS,  // C
        NHH);

    // softmax(scale * scores + mask) -> attnp
    softmax_kernel<<<BB * NHH * SS, 256>>>(scores, mask, attnp,
                                           1.0f / sqrtf((float)HDD));

    // ctx[b,:,h*HD:..] = attn[b,h] @ V[b]   M=S,N=HD,K=S
    gemm_kernel<false><<<dim3(HDD / 128, SS / 128, BB * NHH), 256>>>(
        attnp, v, ctx, SS, HDD, SS,
        SS, NKVV * HDD, NHH * HDD,
        (long long)NHH * SS * SS, (long long)SS * SS,  // A
        (long long)SS * NKVV * HDD, 0,                 // B
        (long long)SS * NHH * HDD, HDD,                // C
        NHH);

    // out = ctx @ Wo   [4096,2048]
    gemm_kernel<false><<<dim3(HIDD / 128, M / 128, 1), 256>>>(
        ctx, Wo, out, M, HIDD, NHH * HDD, NHH * HDD, HIDD, HIDD,
        0, 0, 0, 0, 0, 0, 1);
}